// round 10
// baseline (speedup 1.0000x reference)
#include <cuda_runtime.h>
#include <math.h>

// Problem constants (fixed shapes from reference)
#define NQ      262144      // total queries = B*L*cg = 4*1024*64
#define NSAM    1024        // prior samples
#define THREADS 448
#define QPT     8           // queries per thread-PAIR (4 f32x2 lane-packs)
#define NPACK   4           // QPT/2 lane-packs
#define SPLIT   2           // threads per query-oct (each scans NSAM/SPLIT samples)
#define CHUNK   16          // samples per argmax chunk
#define NCHUNK  (NSAM / CHUNK)          // 64 total
#define CH_PER_THREAD (NCHUNK / SPLIT)  // 32 per thread
#define ZHAT_OFF   0
#define NOQ_OFF    1048576  // B*L*C
#define IDX_OFF    2097152  // 2*B*L*C
#define FULL_OUT   2359296  // + B*L*cg

// ---- packed f32x2 helpers (Blackwell FFMA2/FMUL2) ----
__device__ __forceinline__ unsigned long long ffma2(unsigned long long a,
                                                    unsigned long long b,
                                                    unsigned long long c) {
    unsigned long long d;
    asm("fma.rn.f32x2 %0, %1, %2, %3;" : "=l"(d) : "l"(a), "l"(b), "l"(c));
    return d;
}
__device__ __forceinline__ unsigned long long fmul2(unsigned long long a,
                                                    unsigned long long b) {
    unsigned long long d;
    asm("mul.rn.f32x2 %0, %1, %2;" : "=l"(d) : "l"(a), "l"(b));
    return d;
}
__device__ __forceinline__ unsigned long long packxy(float lo, float hi) {  // (lo, hi)
    unsigned long long r;
    asm("mov.b64 %0, {%1, %2};" : "=l"(r) : "f"(lo), "f"(hi));
    return r;
}
__device__ __forceinline__ float lo2(unsigned long long a) {
    return __uint_as_float((unsigned)(a & 0xffffffffull));
}
__device__ __forceinline__ float hi2(unsigned long long a) {
    return __uint_as_float((unsigned)(a >> 32));
}

// Packed score of TWO queries (in lanes) against ONE sample.
// Sample operands arrive pre-duplicated from the smem table.
// Main loop and rescan share this sequence -> bit-identical recompute.
__device__ __forceinline__ unsigned long long score2(
        const unsigned long long* u, const unsigned long long* vh,
        unsigned long long s0, unsigned long long s1,
        unsigned long long s2, unsigned long long s3) {
    unsigned long long t, a;
    t = ffma2(vh[0], s0, u[0]);  a = fmul2(s0, t);
    t = ffma2(vh[1], s1, u[1]);  a = ffma2(s1, t, a);
    t = ffma2(vh[2], s2, u[2]);  a = ffma2(s2, t, a);
    t = ffma2(vh[3], s3, u[3]);  a = ffma2(s3, t, a);
    return a;
}

// Recompute one chunk for one lane-pack; return smallest sample index whose
// selected lane equals target exactly.
__device__ __forceinline__ int rescan_chunk(const float* __restrict__ tabd,
                                            const unsigned long long* u,
                                            const unsigned long long* vh,
                                            int chunk, float target, int odd) {
    int found = NSAM;
    #pragma unroll 4
    for (int t = 0; t < CHUNK; t++) {
        int n = chunk * CHUNK + t;
        const ulonglong2* sp = reinterpret_cast<const ulonglong2*>(tabd + n * 8);
        ulonglong2 wa = sp[0];   // (s0,s0),(s1,s1)
        ulonglong2 wb = sp[1];   // (s2,s2),(s3,s3)
        unsigned long long a = score2(u, vh, wa.x, wa.y, wb.x, wb.y);
        float v = odd ? hi2(a) : lo2(a);
        if (v == target) found = min(found, n);
    }
    return found;
}

__global__ void __launch_bounds__(THREADS, 1)
gq_kernel(const float* __restrict__ z,
          const float* __restrict__ eps,
          const float* __restrict__ prior,
          float* __restrict__ out,
          int out_size)
{
    // Pre-duplicated sample table: row n = [s0,s0,s1,s1,s2,s2,s3,s3]
    // -> two LDS.128 yield lane-duplicated f32x2 operands with zero MOVs.
    __shared__ __align__(16) float tabd[NSAM * 8];   // 32768 B

    const int tid = threadIdx.x;
    for (int n = tid; n < NSAM; n += THREADS) {
        float4 s = reinterpret_cast<const float4*>(prior)[n];
        float4* t = reinterpret_cast<float4*>(tabd + n * 8);
        t[0] = make_float4(s.x, s.x, s.y, s.y);
        t[1] = make_float4(s.z, s.z, s.w, s.w);
    }

    // Adjacent thread pair (2i, 2i+1) owns query-oct i; h = which sample half.
    const int gtid  = blockIdx.x * THREADS + tid;
    const int octid = gtid >> 1;
    const int h     = gtid & 1;
    const int k0    = octid * QPT;
    const bool valid = (k0 < NQ);   // boundary at thread 65536: warp-aligned
    const int bl = k0 >> 6;     // (b*L + l)
    const int j  = k0 & 63;     // multiple of 8

    // Lane-packed per-query coefficients: pack p covers queries (2p, 2p+1)
    unsigned long long u[NPACK][4], vh[NPACK][4];

    if (valid) {
        #pragma unroll
        for (int g = 0; g < 4; g++) {
            const int moff = bl * 512 + g * 64 + j;           // mu
            float4 ma = *reinterpret_cast<const float4*>(z + moff);
            float4 mb = *reinterpret_cast<const float4*>(z + moff + 4);
            float4 la = *reinterpret_cast<const float4*>(z + moff + 256);
            float4 lb = *reinterpret_cast<const float4*>(z + moff + 260);
            la.x = fminf(fmaxf(la.x, -30.0f), 20.0f);
            la.y = fminf(fmaxf(la.y, -30.0f), 20.0f);
            la.z = fminf(fmaxf(la.z, -30.0f), 20.0f);
            la.w = fminf(fmaxf(la.w, -30.0f), 20.0f);
            lb.x = fminf(fmaxf(lb.x, -30.0f), 20.0f);
            lb.y = fminf(fmaxf(lb.y, -30.0f), 20.0f);
            lb.z = fminf(fmaxf(lb.z, -30.0f), 20.0f);
            lb.w = fminf(fmaxf(lb.w, -30.0f), 20.0f);
            float iv0 = expf(-la.x), iv1 = expf(-la.y);
            float iv2 = expf(-la.z), iv3 = expf(-la.w);
            float iv4 = expf(-lb.x), iv5 = expf(-lb.y);
            float iv6 = expf(-lb.z), iv7 = expf(-lb.w);
            u[0][g]  = packxy(ma.x * iv0, ma.y * iv1);
            u[1][g]  = packxy(ma.z * iv2, ma.w * iv3);
            u[2][g]  = packxy(mb.x * iv4, mb.y * iv5);
            u[3][g]  = packxy(mb.z * iv6, mb.w * iv7);
            vh[0][g] = packxy(0.5f * (1.0f - iv0), 0.5f * (1.0f - iv1));
            vh[1][g] = packxy(0.5f * (1.0f - iv2), 0.5f * (1.0f - iv3));
            vh[2][g] = packxy(0.5f * (1.0f - iv4), 0.5f * (1.0f - iv5));
            vh[3][g] = packxy(0.5f * (1.0f - iv6), 0.5f * (1.0f - iv7));

            // Fused zhat_noquant (written once per oct, by the h==0 thread)
            if (h == 0 && out_size >= IDX_OFF) {
                const int eoff = bl * 256 + g * 64 + j;
                float4 ea = *reinterpret_cast<const float4*>(eps + eoff);
                float4 eb = *reinterpret_cast<const float4*>(eps + eoff + 4);
                float4 na, nb;
                na.x = fmaf(ea.x, expf(0.5f * la.x), ma.x);
                na.y = fmaf(ea.y, expf(0.5f * la.y), ma.y);
                na.z = fmaf(ea.z, expf(0.5f * la.z), ma.z);
                na.w = fmaf(ea.w, expf(0.5f * la.w), ma.w);
                nb.x = fmaf(eb.x, expf(0.5f * lb.x), mb.x);
                nb.y = fmaf(eb.y, expf(0.5f * lb.y), mb.y);
                nb.z = fmaf(eb.z, expf(0.5f * lb.z), mb.z);
                nb.w = fmaf(eb.w, expf(0.5f * lb.w), mb.w);
                *reinterpret_cast<float4*>(out + NOQ_OFF + eoff)     = na;
                *reinterpret_cast<float4*>(out + NOQ_OFF + eoff + 4) = nb;
            }
        }
    }
    __syncthreads();
    if (!valid) return;   // whole warps exit; shuffles below stay full-warp

    const float NEG_INF = -__int_as_float(0x7f800000);
    float gm[QPT];
    int   gc[QPT];
    #pragma unroll
    for (int q = 0; q < QPT; q++) { gm[q] = NEG_INF; gc[q] = 0; }

    // This thread scans chunks [h*32, h*32+32) = samples [h*512, h*512+512)
    const int ch0 = h * CH_PER_THREAD;
    for (int ci = 0; ci < CH_PER_THREAD; ci++) {
        const int ch = ch0 + ci;
        float me[QPT];
        #pragma unroll
        for (int q = 0; q < QPT; q++) me[q] = NEG_INF;

        const float* cbase = tabd + ch * CHUNK * 8;
        #pragma unroll
        for (int t = 0; t < CHUNK; t++) {
            const ulonglong2* sp = reinterpret_cast<const ulonglong2*>(cbase + t * 8);
            ulonglong2 wa = sp[0];   // (s0,s0),(s1,s1)
            ulonglong2 wb = sp[1];   // (s2,s2),(s3,s3)
            #pragma unroll
            for (int p = 0; p < NPACK; p++) {
                unsigned long long a = score2(u[p], vh[p], wa.x, wa.y, wb.x, wb.y);
                me[2 * p]     = fmaxf(me[2 * p],     lo2(a));
                me[2 * p + 1] = fmaxf(me[2 * p + 1], hi2(a));
            }
        }
        // Strict '>' keeps the earliest chunk on ties (first-index semantics)
        #pragma unroll
        for (int q = 0; q < QPT; q++)
            if (me[q] > gm[q]) { gm[q] = me[q]; gc[q] = ch; }
    }

    // Merge the two halves across the thread pair (xor-1 shuffle).
    // On equal max, smaller chunk id wins -> global first-index semantics.
    #pragma unroll
    for (int q = 0; q < QPT; q++) {
        float pm = __shfl_xor_sync(0xFFFFFFFFu, gm[q], 1);
        int   pc = __shfl_xor_sync(0xFFFFFFFFu, gc[q], 1);
        if (pm > gm[q] || (pm == gm[q] && pc < gc[q])) { gm[q] = pm; gc[q] = pc; }
    }

    if (h != 0) return;   // odd thread done; even thread resolves + writes

    // Resolve exact indices by rescanning each query's winning chunk
    int bidx[QPT];
    #pragma unroll
    for (int q = 0; q < QPT; q++)
        bidx[q] = rescan_chunk(tabd, u[q >> 1], vh[q >> 1], gc[q], gm[q], q & 1);

    {
        // Gather winning prior rows (prior is L2-hot, 16 KB)
        float r[QPT][4];
        #pragma unroll
        for (int q = 0; q < QPT; q++) {
            float4 s = reinterpret_cast<const float4*>(prior)[bidx[q]];
            r[q][0] = s.x; r[q][1] = s.y; r[q][2] = s.z; r[q][3] = s.w;
        }
        const int obase = bl * 256 + j;
        #pragma unroll
        for (int g = 0; g < 4; g++) {
            *reinterpret_cast<float4*>(out + ZHAT_OFF + obase + g * 64) =
                make_float4(r[0][g], r[1][g], r[2][g], r[3][g]);
            *reinterpret_cast<float4*>(out + ZHAT_OFF + obase + g * 64 + 4) =
                make_float4(r[4][g], r[5][g], r[6][g], r[7][g]);
        }
        if (out_size >= FULL_OUT) {
            *reinterpret_cast<float4*>(out + IDX_OFF + k0) =
                make_float4((float)bidx[0], (float)bidx[1],
                            (float)bidx[2], (float)bidx[3]);
            *reinterpret_cast<float4*>(out + IDX_OFF + k0 + 4) =
                make_float4((float)bidx[4], (float)bidx[5],
                            (float)bidx[6], (float)bidx[7]);
        }
    }
}

extern "C" void kernel_launch(void* const* d_in, const int* in_sizes, int n_in,
                              void* d_out, int out_size) {
    const float* z     = (const float*)d_in[0];
    const float* eps   = (const float*)d_in[1];
    const float* prior = (const float*)d_in[2];
    (void)in_sizes; (void)n_in;
    const int thread_slots = (NQ / QPT) * SPLIT;               // 65536
    const int blocks = (thread_slots + THREADS - 1) / THREADS; // 147 -> one wave
    gq_kernel<<<blocks, THREADS>>>(z, eps, prior, (float*)d_out, out_size);
}

// round 11
// speedup vs baseline: 1.0248x; 1.0248x over previous
#include <cuda_runtime.h>
#include <math.h>

// Problem constants (fixed shapes from reference)
#define NQ      262144      // total queries = B*L*cg = 4*1024*64
#define NSAM    1024        // prior samples
#define THREADS 448
#define QPT     4           // queries per thread-PAIR (2 f32x2 lane-packs)
#define SPLIT   2           // threads per query-quad (each scans NSAM/SPLIT samples)
#define CHUNK   16          // samples per argmax chunk
#define NCHUNK  (NSAM / CHUNK)          // 64 total
#define CH_PER_THREAD (NCHUNK / SPLIT)  // 32 per thread
#define ZHAT_OFF   0
#define NOQ_OFF    1048576  // B*L*C
#define IDX_OFF    2097152  // 2*B*L*C
#define FULL_OUT   2359296  // + B*L*cg

// ---- packed f32x2 helpers (Blackwell FFMA2/FMUL2) ----
__device__ __forceinline__ unsigned long long ffma2(unsigned long long a,
                                                    unsigned long long b,
                                                    unsigned long long c) {
    unsigned long long d;
    asm("fma.rn.f32x2 %0, %1, %2, %3;" : "=l"(d) : "l"(a), "l"(b), "l"(c));
    return d;
}
__device__ __forceinline__ unsigned long long fmul2(unsigned long long a,
                                                    unsigned long long b) {
    unsigned long long d;
    asm("mul.rn.f32x2 %0, %1, %2;" : "=l"(d) : "l"(a), "l"(b));
    return d;
}
__device__ __forceinline__ unsigned long long packxy(float lo, float hi) {  // (lo, hi)
    unsigned long long r;
    asm("mov.b64 %0, {%1, %2};" : "=l"(r) : "f"(lo), "f"(hi));
    return r;
}
__device__ __forceinline__ float lo2(unsigned long long a) {
    return __uint_as_float((unsigned)(a & 0xffffffffull));
}
__device__ __forceinline__ float hi2(unsigned long long a) {
    return __uint_as_float((unsigned)(a >> 32));
}

// Packed score of TWO queries (in lanes) against ONE sample.
// Sample operands arrive pre-duplicated from the smem table (no MOVs).
// Main loop and rescan share this sequence -> bit-identical recompute.
__device__ __forceinline__ unsigned long long score2(
        const unsigned long long* u, const unsigned long long* vh,
        unsigned long long s0, unsigned long long s1,
        unsigned long long s2, unsigned long long s3) {
    unsigned long long t, a;
    t = ffma2(vh[0], s0, u[0]);  a = fmul2(s0, t);
    t = ffma2(vh[1], s1, u[1]);  a = ffma2(s1, t, a);
    t = ffma2(vh[2], s2, u[2]);  a = ffma2(s2, t, a);
    t = ffma2(vh[3], s3, u[3]);  a = ffma2(s3, t, a);
    return a;
}

// Recompute one chunk for one lane-pack; return smallest sample index whose
// selected lane equals target exactly.
__device__ __forceinline__ int rescan_chunk(const float* __restrict__ tabd,
                                            const unsigned long long* u,
                                            const unsigned long long* vh,
                                            int chunk, float target, int odd) {
    int found = NSAM;
    #pragma unroll 4
    for (int t = 0; t < CHUNK; t++) {
        int n = chunk * CHUNK + t;
        const ulonglong2* sp = reinterpret_cast<const ulonglong2*>(tabd + n * 8);
        ulonglong2 wa = sp[0];   // (s0,s0),(s1,s1)
        ulonglong2 wb = sp[1];   // (s2,s2),(s3,s3)
        unsigned long long a = score2(u, vh, wa.x, wa.y, wb.x, wb.y);
        float v = odd ? hi2(a) : lo2(a);
        if (v == target) found = min(found, n);
    }
    return found;
}

__global__ void __launch_bounds__(THREADS, 2)
gq_kernel(const float* __restrict__ z,
          const float* __restrict__ eps,
          const float* __restrict__ prior,
          float* __restrict__ out,
          int out_size)
{
    // Pre-duplicated sample table: row n = [s0,s0,s1,s1,s2,s2,s3,s3]
    // -> two LDS.128 yield lane-duplicated f32x2 operands with zero MOVs.
    __shared__ __align__(16) float tabd[NSAM * 8];   // 32768 B per CTA

    const int tid = threadIdx.x;
    for (int n = tid; n < NSAM; n += THREADS) {
        float4 s = reinterpret_cast<const float4*>(prior)[n];
        float4* t = reinterpret_cast<float4*>(tabd + n * 8);
        t[0] = make_float4(s.x, s.x, s.y, s.y);
        t[1] = make_float4(s.z, s.z, s.w, s.w);
    }

    // Adjacent thread pair (2i, 2i+1) owns query-quad i; h = which sample half.
    const int gtid   = blockIdx.x * THREADS + tid;
    const int pairid = gtid >> 1;
    const int h      = gtid & 1;
    const int k0     = pairid * QPT;
    const bool valid = (k0 < NQ);   // boundary warp-aligned (pairs adjacent)
    const int bl = k0 >> 6;     // (b*L + l)
    const int j  = k0 & 63;

    // Lane-packed per-query coefficients: u01[g]=(u_q0,u_q1), u23[g]=(u_q2,u_q3)
    unsigned long long u01[4], u23[4], vh01[4], vh23[4];

    if (valid) {
        #pragma unroll
        for (int g = 0; g < 4; g++) {
            const int moff = bl * 512 + g * 64 + j;           // mu
            float4 mu4 = *reinterpret_cast<const float4*>(z + moff);
            float4 lv4 = *reinterpret_cast<const float4*>(z + moff + 256);
            lv4.x = fminf(fmaxf(lv4.x, -30.0f), 20.0f);
            lv4.y = fminf(fmaxf(lv4.y, -30.0f), 20.0f);
            lv4.z = fminf(fmaxf(lv4.z, -30.0f), 20.0f);
            lv4.w = fminf(fmaxf(lv4.w, -30.0f), 20.0f);
            float ivx = expf(-lv4.x), ivy = expf(-lv4.y);
            float ivz = expf(-lv4.z), ivw = expf(-lv4.w);
            u01[g]  = packxy(mu4.x * ivx, mu4.y * ivy);
            u23[g]  = packxy(mu4.z * ivz, mu4.w * ivw);
            vh01[g] = packxy(0.5f * (1.0f - ivx), 0.5f * (1.0f - ivy));
            vh23[g] = packxy(0.5f * (1.0f - ivz), 0.5f * (1.0f - ivw));

            // Fused zhat_noquant (written once per quad, by the h==0 thread)
            if (h == 0 && out_size >= IDX_OFF) {
                const int eoff = bl * 256 + g * 64 + j;
                float4 e4 = *reinterpret_cast<const float4*>(eps + eoff);
                float4 nq;
                nq.x = fmaf(e4.x, expf(0.5f * lv4.x), mu4.x);
                nq.y = fmaf(e4.y, expf(0.5f * lv4.y), mu4.y);
                nq.z = fmaf(e4.z, expf(0.5f * lv4.z), mu4.z);
                nq.w = fmaf(e4.w, expf(0.5f * lv4.w), mu4.w);
                *reinterpret_cast<float4*>(out + NOQ_OFF + eoff) = nq;
            }
        }
    }
    __syncthreads();
    if (!valid) return;   // whole warps exit; shuffles below stay full-warp

    const float NEG_INF = -__int_as_float(0x7f800000);
    float gm[QPT];
    int   gc[QPT];
    #pragma unroll
    for (int q = 0; q < QPT; q++) { gm[q] = NEG_INF; gc[q] = 0; }

    // This thread scans chunks [h*32, h*32+32) = samples [h*512, h*512+512)
    const int ch0 = h * CH_PER_THREAD;
    for (int ci = 0; ci < CH_PER_THREAD; ci++) {
        const int ch = ch0 + ci;
        float m0 = NEG_INF, m1 = NEG_INF, m2 = NEG_INF, m3 = NEG_INF;
        const float* cbase = tabd + ch * CHUNK * 8;
        #pragma unroll
        for (int t = 0; t < CHUNK; t++) {
            const ulonglong2* sp = reinterpret_cast<const ulonglong2*>(cbase + t * 8);
            ulonglong2 wa = sp[0];   // (s0,s0),(s1,s1)
            ulonglong2 wb = sp[1];   // (s2,s2),(s3,s3)
            unsigned long long a01 = score2(u01, vh01, wa.x, wa.y, wb.x, wb.y);
            unsigned long long a23 = score2(u23, vh23, wa.x, wa.y, wb.x, wb.y);
            m0 = fmaxf(m0, lo2(a01));
            m1 = fmaxf(m1, hi2(a01));
            m2 = fmaxf(m2, lo2(a23));
            m3 = fmaxf(m3, hi2(a23));
        }
        // Strict '>' keeps the earliest chunk on ties (first-index semantics)
        if (m0 > gm[0]) { gm[0] = m0; gc[0] = ch; }
        if (m1 > gm[1]) { gm[1] = m1; gc[1] = ch; }
        if (m2 > gm[2]) { gm[2] = m2; gc[2] = ch; }
        if (m3 > gm[3]) { gm[3] = m3; gc[3] = ch; }
    }

    // Merge the two halves across the thread pair (xor-1 shuffle).
    // On equal max, smaller chunk id wins -> global first-index semantics.
    #pragma unroll
    for (int q = 0; q < QPT; q++) {
        float pm = __shfl_xor_sync(0xFFFFFFFFu, gm[q], 1);
        int   pc = __shfl_xor_sync(0xFFFFFFFFu, gc[q], 1);
        if (pm > gm[q] || (pm == gm[q] && pc < gc[q])) { gm[q] = pm; gc[q] = pc; }
    }

    if (h != 0) return;   // odd thread done; even thread resolves + writes

    // Resolve exact indices by rescanning each query's winning chunk
    int bidx[QPT];
    bidx[0] = rescan_chunk(tabd, u01, vh01, gc[0], gm[0], 0);
    bidx[1] = rescan_chunk(tabd, u01, vh01, gc[1], gm[1], 1);
    bidx[2] = rescan_chunk(tabd, u23, vh23, gc[2], gm[2], 0);
    bidx[3] = rescan_chunk(tabd, u23, vh23, gc[3], gm[3], 1);

    {
        // Gather winning prior rows (prior is L2-hot, 16 KB)
        float r[QPT][4];
        #pragma unroll
        for (int q = 0; q < QPT; q++) {
            float4 s = reinterpret_cast<const float4*>(prior)[bidx[q]];
            r[q][0] = s.x; r[q][1] = s.y; r[q][2] = s.z; r[q][3] = s.w;
        }
        const int obase = bl * 256 + j;
        #pragma unroll
        for (int g = 0; g < 4; g++) {
            float4 o4 = make_float4(r[0][g], r[1][g], r[2][g], r[3][g]);
            *reinterpret_cast<float4*>(out + ZHAT_OFF + obase + g * 64) = o4;
        }
        if (out_size >= FULL_OUT) {
            float4 i4 = make_float4((float)bidx[0], (float)bidx[1],
                                    (float)bidx[2], (float)bidx[3]);
            *reinterpret_cast<float4*>(out + IDX_OFF + k0) = i4;
        }
    }
}

extern "C" void kernel_launch(void* const* d_in, const int* in_sizes, int n_in,
                              void* d_out, int out_size) {
    const float* z     = (const float*)d_in[0];
    const float* eps   = (const float*)d_in[1];
    const float* prior = (const float*)d_in[2];
    (void)in_sizes; (void)n_in;
    const int thread_slots = (NQ / QPT) * SPLIT;               // 131072
    const int blocks = (thread_slots + THREADS - 1) / THREADS; // 293 -> 2 CTAs/SM
    gq_kernel<<<blocks, THREADS>>>(z, eps, prior, (float*)d_out, out_size);
}

// round 12
// speedup vs baseline: 1.3616x; 1.3287x over previous
#include <cuda_runtime.h>
#include <math.h>

// Problem constants (fixed shapes from reference)
#define NQ      262144      // total queries = B*L*cg = 4*1024*64
#define NSAM    1024        // prior samples
#define THREADS 448
#define QPT     4           // queries per thread-PAIR (2 f32x2 lane-packs)
#define SPLIT   2           // threads per query-quad (each scans NSAM/SPLIT samples)
#define CHUNK   16          // samples per argmax chunk
#define NCHUNK  (NSAM / CHUNK)          // 64 total
#define CH_PER_THREAD (NCHUNK / SPLIT)  // 32 per thread
#define ZHAT_OFF   0
#define NOQ_OFF    1048576  // B*L*C
#define IDX_OFF    2097152  // 2*B*L*C
#define FULL_OUT   2359296  // + B*L*cg

// ---- packed f32x2 helpers (Blackwell FFMA2/FMUL2) ----
__device__ __forceinline__ unsigned long long ffma2(unsigned long long a,
                                                    unsigned long long b,
                                                    unsigned long long c) {
    unsigned long long d;
    asm("fma.rn.f32x2 %0, %1, %2, %3;" : "=l"(d) : "l"(a), "l"(b), "l"(c));
    return d;
}
__device__ __forceinline__ unsigned long long fmul2(unsigned long long a,
                                                    unsigned long long b) {
    unsigned long long d;
    asm("mul.rn.f32x2 %0, %1, %2;" : "=l"(d) : "l"(a), "l"(b));
    return d;
}
__device__ __forceinline__ unsigned long long pack2(float x) {     // (x, x)
    unsigned long long r;
    asm("mov.b64 %0, {%1, %1};" : "=l"(r) : "f"(x));
    return r;
}
__device__ __forceinline__ unsigned long long packxy(float lo, float hi) {  // (lo, hi)
    unsigned long long r;
    asm("mov.b64 %0, {%1, %2};" : "=l"(r) : "f"(lo), "f"(hi));
    return r;
}
__device__ __forceinline__ float lo2(unsigned long long a) {
    return __uint_as_float((unsigned)(a & 0xffffffffull));
}
__device__ __forceinline__ float hi2(unsigned long long a) {
    return __uint_as_float((unsigned)(a >> 32));
}

// Packed score of TWO queries (in lanes) against ONE sample.
// Main loop and rescan share this sequence -> bit-identical recompute.
__device__ __forceinline__ unsigned long long score2(
        const unsigned long long* u, const unsigned long long* vh,
        unsigned long long s0, unsigned long long s1,
        unsigned long long s2, unsigned long long s3) {
    unsigned long long t, a;
    t = ffma2(vh[0], s0, u[0]);  a = fmul2(s0, t);
    t = ffma2(vh[1], s1, u[1]);  a = ffma2(s1, t, a);
    t = ffma2(vh[2], s2, u[2]);  a = ffma2(s2, t, a);
    t = ffma2(vh[3], s3, u[3]);  a = ffma2(s3, t, a);
    return a;
}

// Recompute one chunk for one lane-pack; return smallest sample index whose
// selected lane equals target exactly.
__device__ __forceinline__ int rescan_chunk(const float4* __restrict__ tab,
                                            const unsigned long long* u,
                                            const unsigned long long* vh,
                                            int chunk, float target, int odd) {
    int found = NSAM;
    #pragma unroll 4
    for (int t = 0; t < CHUNK; t++) {
        int n = chunk * CHUNK + t;
        float4 s = tab[n];
        unsigned long long a = score2(u, vh, pack2(s.x), pack2(s.y),
                                             pack2(s.z), pack2(s.w));
        float v = odd ? hi2(a) : lo2(a);
        if (v == target) found = min(found, n);
    }
    return found;
}

__global__ void __launch_bounds__(THREADS, 2)
gq_kernel(const float* __restrict__ z,
          const float* __restrict__ eps,
          const float* __restrict__ prior,
          float* __restrict__ out,
          int out_size)
{
    // Sample table = raw prior rows: tab[n] = (S_g0, S_g1, S_g2, S_g3)
    __shared__ __align__(16) float4 tab[NSAM];     // 16384 B

    const int tid = threadIdx.x;
    for (int n = tid; n < NSAM; n += THREADS)
        tab[n] = reinterpret_cast<const float4*>(prior)[n];

    // Adjacent thread pair (2i, 2i+1) owns query-quad i; h = which sample half.
    const int gtid   = blockIdx.x * THREADS + tid;
    const int pairid = gtid >> 1;
    const int h      = gtid & 1;
    const int k0     = pairid * QPT;
    const bool valid = (k0 < NQ);   // boundary warp-aligned (pairs adjacent)
    const int bl = k0 >> 6;     // (b*L + l)
    const int j  = k0 & 63;

    // Lane-packed per-query coefficients: u01[g]=(u_q0,u_q1), u23[g]=(u_q2,u_q3)
    unsigned long long u01[4], u23[4], vh01[4], vh23[4];

    if (valid) {
        #pragma unroll
        for (int g = 0; g < 4; g++) {
            const int moff = bl * 512 + g * 64 + j;           // mu
            float4 mu4 = *reinterpret_cast<const float4*>(z + moff);
            float4 lv4 = *reinterpret_cast<const float4*>(z + moff + 256);
            lv4.x = fminf(fmaxf(lv4.x, -30.0f), 20.0f);
            lv4.y = fminf(fmaxf(lv4.y, -30.0f), 20.0f);
            lv4.z = fminf(fmaxf(lv4.z, -30.0f), 20.0f);
            lv4.w = fminf(fmaxf(lv4.w, -30.0f), 20.0f);
            float ivx = expf(-lv4.x), ivy = expf(-lv4.y);
            float ivz = expf(-lv4.z), ivw = expf(-lv4.w);
            u01[g]  = packxy(mu4.x * ivx, mu4.y * ivy);
            u23[g]  = packxy(mu4.z * ivz, mu4.w * ivw);
            vh01[g] = packxy(0.5f * (1.0f - ivx), 0.5f * (1.0f - ivy));
            vh23[g] = packxy(0.5f * (1.0f - ivz), 0.5f * (1.0f - ivw));

            // Fused zhat_noquant (written once per quad, by the h==0 thread)
            if (h == 0 && out_size >= IDX_OFF) {
                const int eoff = bl * 256 + g * 64 + j;
                float4 e4 = *reinterpret_cast<const float4*>(eps + eoff);
                float4 nq;
                nq.x = fmaf(e4.x, expf(0.5f * lv4.x), mu4.x);
                nq.y = fmaf(e4.y, expf(0.5f * lv4.y), mu4.y);
                nq.z = fmaf(e4.z, expf(0.5f * lv4.z), mu4.z);
                nq.w = fmaf(e4.w, expf(0.5f * lv4.w), mu4.w);
                *reinterpret_cast<float4*>(out + NOQ_OFF + eoff) = nq;
            }
        }
    }
    __syncthreads();
    if (!valid) return;   // whole warps exit; shuffles below stay full-warp

    const float NEG_INF = -__int_as_float(0x7f800000);
    float gm[QPT];
    int   gc[QPT];
    #pragma unroll
    for (int q = 0; q < QPT; q++) { gm[q] = NEG_INF; gc[q] = 0; }

    // This thread scans chunks [h*32, h*32+32) = samples [h*512, h*512+512)
    const int ch0 = h * CH_PER_THREAD;
    #pragma unroll 2
    for (int ci = 0; ci < CH_PER_THREAD; ci++) {
        const int ch = ch0 + ci;
        float m0 = NEG_INF, m1 = NEG_INF, m2 = NEG_INF, m3 = NEG_INF;
        const float4* cbase = &tab[ch * CHUNK];
        #pragma unroll
        for (int t = 0; t < CHUNK; t++) {
            float4 s = cbase[t];                       // one LDS.128 per sample
            unsigned long long s0 = pack2(s.x), s1 = pack2(s.y);
            unsigned long long s2 = pack2(s.z), s3 = pack2(s.w);
            unsigned long long a01 = score2(u01, vh01, s0, s1, s2, s3);
            unsigned long long a23 = score2(u23, vh23, s0, s1, s2, s3);
            m0 = fmaxf(m0, lo2(a01));
            m1 = fmaxf(m1, hi2(a01));
            m2 = fmaxf(m2, lo2(a23));
            m3 = fmaxf(m3, hi2(a23));
        }
        // Strict '>' keeps the earliest chunk on ties (first-index semantics)
        if (m0 > gm[0]) { gm[0] = m0; gc[0] = ch; }
        if (m1 > gm[1]) { gm[1] = m1; gc[1] = ch; }
        if (m2 > gm[2]) { gm[2] = m2; gc[2] = ch; }
        if (m3 > gm[3]) { gm[3] = m3; gc[3] = ch; }
    }

    // Merge the two halves across the thread pair (xor-1 shuffle).
    // On equal max, smaller chunk id wins -> global first-index semantics.
    #pragma unroll
    for (int q = 0; q < QPT; q++) {
        float pm = __shfl_xor_sync(0xFFFFFFFFu, gm[q], 1);
        int   pc = __shfl_xor_sync(0xFFFFFFFFu, gc[q], 1);
        if (pm > gm[q] || (pm == gm[q] && pc < gc[q])) { gm[q] = pm; gc[q] = pc; }
    }

    // Parallel rescan: even thread resolves q0,q1; odd thread resolves q2,q3.
    // Coefficients are bit-identical in both threads of the pair, so the
    // recompute stays exact. Select operands with SELs (no indexed arrays).
    unsigned long long ua[4], va[4];
    #pragma unroll
    for (int g = 0; g < 4; g++) {
        ua[g] = h ? u23[g]  : u01[g];
        va[g] = h ? vh23[g] : vh01[g];
    }
    const int   ca0 = h ? gc[2] : gc[0];
    const int   ca1 = h ? gc[3] : gc[1];
    const float ta0 = h ? gm[2] : gm[0];
    const float ta1 = h ? gm[3] : gm[1];
    int ra = rescan_chunk(tab, ua, va, ca0, ta0, 0);   // lane 0 of this pack
    int rb = rescan_chunk(tab, ua, va, ca1, ta1, 1);   // lane 1 of this pack

    int pra = __shfl_xor_sync(0xFFFFFFFFu, ra, 1);
    int prb = __shfl_xor_sync(0xFFFFFFFFu, rb, 1);

    if (h != 0) return;   // odd thread done; even thread writes

    int bidx[QPT];
    bidx[0] = ra;  bidx[1] = rb;  bidx[2] = pra;  bidx[3] = prb;

    {
        // Gather winning prior rows from the smem table
        float r[QPT][4];
        #pragma unroll
        for (int q = 0; q < QPT; q++) {
            float4 s = tab[bidx[q]];
            r[q][0] = s.x; r[q][1] = s.y; r[q][2] = s.z; r[q][3] = s.w;
        }
        const int obase = bl * 256 + j;
        #pragma unroll
        for (int g = 0; g < 4; g++) {
            float4 o4 = make_float4(r[0][g], r[1][g], r[2][g], r[3][g]);
            *reinterpret_cast<float4*>(out + ZHAT_OFF + obase + g * 64) = o4;
        }
        if (out_size >= FULL_OUT) {
            float4 i4 = make_float4((float)bidx[0], (float)bidx[1],
                                    (float)bidx[2], (float)bidx[3]);
            *reinterpret_cast<float4*>(out + IDX_OFF + k0) = i4;
        }
    }
}

extern "C" void kernel_launch(void* const* d_in, const int* in_sizes, int n_in,
                              void* d_out, int out_size) {
    const float* z     = (const float*)d_in[0];
    const float* eps   = (const float*)d_in[1];
    const float* prior = (const float*)d_in[2];
    (void)in_sizes; (void)n_in;
    const int thread_slots = (NQ / QPT) * SPLIT;               // 131072
    const int blocks = (thread_slots + THREADS - 1) / THREADS; // 293 -> 2 CTAs/SM
    gq_kernel<<<blocks, THREADS>>>(z, eps, prior, (float*)d_out, out_size);
}